// round 14
// baseline (speedup 1.0000x reference)
#include <cuda_runtime.h>
#include <cuda_fp16.h>
#include <cuda_bf16.h>
#include <cstdint>
#include <cstddef>

// ---------------- problem constants ----------------
#define NA      100000          // atoms
#define MN      12              // neighbors
#define AF      64              // atom feature len
#define NFE     41              // nbr feature len
#define C2      128             // 2*AF
#define NMROWS  (NA*MN)         // 1,200,000 edge rows
#define NB_B2   (NMROWS/128)    // 9375 blocks in gemm pass (128 rows/block)
#define NB_C    (NA/16)         // 6250 blocks in apply pass
#define N0C     100             // crystals
#define APC     1000            // atoms per crystal
#define HFD     128
#define HIDD    64
#define EPSV    1e-5f
#define NBR_ELEMS (NMROWS*NFE)  // 49,200,000

typedef unsigned long long ull;

// ---------------- device scratch (no allocations allowed) ----------------
__device__ float  g_atom  [NA*AF];
__device__ float  g_Pself [NA*C2];
__device__ float  g_Pnbr  [NA*C2];
__device__ __half g_gatedh[(size_t)NMROWS*C2];   // 307 MB
__device__ __half g_nbrh  [NBR_ELEMS];           // 98 MB fp16 copy of nbr_fea
__device__ float  g_summed[NA*AF];
__device__ float  g_part1 [256*NB_B2];
__device__ float  g_part2 [128*NB_C];
__device__ float  g_red1  [256];
__device__ float  g_red2  [128];
__device__ float  g_sc1[128], g_sh1[128];
__device__ float  g_sc2[64],  g_sh2[64];

// ---------------- helpers ----------------
__device__ __forceinline__ float softplusf(float x) {
    return fmaxf(x, 0.f) + log1pf(__expf(-fabsf(x)));
}
// fast variants for the bulk k_C pass (error ~1e-6 rel, budget 1e-3)
__device__ __forceinline__ float fsig(float x) {
    return __fdividef(1.f, 1.f + __expf(-x));
}
__device__ __forceinline__ float fsp(float x) {
    return fmaxf(x, 0.f) + __logf(1.f + __expf(-fabsf(x)));
}
// packed f32x2 FMA: d = a*b + d  (two fp32 lanes per issue slot)
__device__ __forceinline__ void ffma2(ull& d, ull a, ull b) {
    asm("fma.rn.f32x2 %0, %1, %2, %0;" : "+l"(d) : "l"(a), "l"(b));
}
__device__ __forceinline__ ull dup2(float v) {
    unsigned int u = __float_as_uint(v);
    ull r;
    asm("mov.b64 %0, {%1, %1};" : "=l"(r) : "r"(u));
    return r;
}
__device__ __forceinline__ float2 lo2(const ull& v) {
    return *reinterpret_cast<const float2*>(&v);
}

// ---------------- k_embed ----------------
__global__ __launch_bounds__(256) void k_embed(const int* __restrict__ atom_num,
                                               const float* __restrict__ emb) {
    int i = blockIdx.x * 256 + threadIdx.x;
    int base = i * 4;
    int n = base >> 6;
    int c = base & 63;
    int a = atom_num[n];
    float4 v = *(const float4*)(emb + a * AF + c);
    *(float4*)(g_atom + base) = v;
}

// ---------------- k_prep: nbr_fea fp32 -> fp16 (once) ----------------
__global__ __launch_bounds__(256) void k_prep(const float* __restrict__ nbrF) {
    int i = blockIdx.x * 256 + threadIdx.x;
    int base = i * 4;
    if (base >= NBR_ELEMS) return;
    float4 v = *(const float4*)(nbrF + base);
    __half2 h0 = __floats2half2_rn(v.x, v.y);
    __half2 h1 = __floats2half2_rn(v.z, v.w);
    uint2 o;
    o.x = *(unsigned int*)&h0;
    o.y = *(unsigned int*)&h1;
    *(uint2*)(g_nbrh + base) = o;
}

// ---------------- k_A2: Pself/Pnbr = atom_fea @ Wslab ----------------
// block: 128 rows x 128 cols, 512 threads (32 rt x 16 ct), thread 4x8.
// Row-paired accumulators: A natural pairs (broadcast LDS.128), W natural
// conflict-free 12-float-stride chunks + register dup.
#define A2_SMEM_A  (64*132*4)              // 33792
#define A2_SMEM_W  (64*192*4)              // 49152
#define A2_SMEM_BYTES (A2_SMEM_A + A2_SMEM_W)   // 82944
__global__ __launch_bounds__(512, 2) void k_A2(const float* __restrict__ W) {
    extern __shared__ unsigned char smraw[];
    float* sA = (float*)smraw;                  // [64 k][132 rows]
    float* sW = (float*)(smraw + A2_SMEM_A);    // [64 k][16 chunks * 12 floats]
    int tid = threadIdx.x;
    int r0 = blockIdx.x * 128;
    int half = blockIdx.y;
    const float* Wslab = W + half * 64 * 128;

    for (int idx = tid; idx < 128*64; idx += 512) {
        int row = idx >> 6, k = idx & 63;
        int r = r0 + row;
        sA[k*132 + row] = (r < NA) ? g_atom[r*AF + k] : 0.f;
    }
    for (int idx = tid; idx < 64*128; idx += 512) {
        int k = idx >> 7, cc = idx & 127;
        int c = cc >> 3, j = cc & 7;
        sW[k*192 + c*12 + j] = Wslab[k*128 + cc];
    }
    __syncthreads();

    int ct = tid & 15, rt = tid >> 4;      // rt 0..31
    int c0 = ct * 8;
    ull acc[2][8];   // [rowpair][col]: lanes = rows 2p, 2p+1 (of this thread's 4)
    #pragma unroll
    for (int p = 0; p < 2; p++)
        #pragma unroll
        for (int j = 0; j < 8; j++) acc[p][j] = 0ULL;

    #pragma unroll 1
    for (int k = 0; k < 64; k++) {
        const ulonglong2* ap = (const ulonglong2*)(sA + k*132 + rt*4);
        ulonglong2 a01 = ap[0];                 // rows 4rt..4rt+3 as 2 pairs
        ull av[2] = {a01.x, a01.y};
        const ulonglong2* wp = (const ulonglong2*)(sW + k*192 + ct*12);
        ulonglong2 wA = wp[0], wB = wp[1];
        float2 w01 = lo2(wA.x), w23 = lo2(wA.y), w45 = lo2(wB.x), w67 = lo2(wB.y);
        ull wd[8] = {dup2(w01.x), dup2(w01.y), dup2(w23.x), dup2(w23.y),
                     dup2(w45.x), dup2(w45.y), dup2(w67.x), dup2(w67.y)};
        #pragma unroll
        for (int p = 0; p < 2; p++)
            #pragma unroll
            for (int j = 0; j < 8; j++)
                ffma2(acc[p][j], av[p], wd[j]);
    }

    float* dst = half ? g_Pnbr : g_Pself;
    #pragma unroll
    for (int i = 0; i < 4; i++) {
        int r = r0 + rt*4 + i;
        if (r < NA) {
            int p = i >> 1, h = i & 1;
            float v[8];
            #pragma unroll
            for (int j = 0; j < 8; j++) {
                float2 f = lo2(acc[p][j]);
                v[j] = h ? f.y : f.x;
            }
            float* pp = dst + r*C2 + c0;
            *(float4*)(pp)     = make_float4(v[0], v[1], v[2], v[3]);
            *(float4*)(pp + 4) = make_float4(v[4], v[5], v[6], v[7]);
        }
    }
}

// ---------------- k_B: edge GEMM + assemble gated(fp16) + bn1 partial stats ----------------
// block: 128 edge-rows x 128 cols, 512 threads (32 rt x 16 ct), thread 4x8.
// Row-paired accumulators; A natural pairs (broadcast); W natural + reg dup.
#define B_SMEM_A   (41*132*4)              // 21648
#define B_SMEM_W   (41*192*4)              // 31488
#define B_SMEM_BYTES (B_SMEM_A + B_SMEM_W + 32*128*4)   // + sbuf 16384 = 69520
__global__ __launch_bounds__(512, 2) void k_B(const int*   __restrict__ nidx,
                                              const float* __restrict__ Wnf,
                                              const float* __restrict__ bias) {
    extern __shared__ unsigned char smraw[];
    float* sA   = (float*)smraw;                          // [41 k][132 rows]
    float* sW   = (float*)(smraw + B_SMEM_A);             // [41 k][16 chunks * 12]
    float* sbuf = (float*)(smraw + B_SMEM_A + B_SMEM_W);  // [32][128]
    int tid = threadIdx.x;
    int r0 = blockIdx.x * 128;

    const __half* src = g_nbrh + (size_t)r0 * NFE;   // 128 contiguous rows
    for (int idx = tid; idx < 128*41; idx += 512) {
        int row = idx / 41, k = idx - row*41;
        sA[k*132 + row] = __half2float(src[idx]);
    }
    for (int idx = tid; idx < 41*128; idx += 512) {
        int k = idx >> 7, cc = idx & 127;
        int c = cc >> 3, j = cc & 7;
        sW[k*192 + c*12 + j] = Wnf[k*128 + cc];
    }
    __syncthreads();

    int ct = tid & 15, rt = tid >> 4;      // rt 0..31
    int c0 = ct * 8;
    ull acc[2][8];   // [rowpair][col]
    #pragma unroll
    for (int p = 0; p < 2; p++)
        #pragma unroll
        for (int j = 0; j < 8; j++) acc[p][j] = 0ULL;

    #pragma unroll 1
    for (int k = 0; k < 41; k++) {
        const ulonglong2* ap = (const ulonglong2*)(sA + k*132 + rt*4);
        ulonglong2 a01 = ap[0];
        ull av[2] = {a01.x, a01.y};
        const ulonglong2* wp = (const ulonglong2*)(sW + k*192 + ct*12);
        ulonglong2 wA = wp[0], wB = wp[1];
        float2 w01 = lo2(wA.x), w23 = lo2(wA.y), w45 = lo2(wB.x), w67 = lo2(wB.y);
        ull wd[8] = {dup2(w01.x), dup2(w01.y), dup2(w23.x), dup2(w23.y),
                     dup2(w45.x), dup2(w45.y), dup2(w67.x), dup2(w67.y)};
        #pragma unroll
        for (int p = 0; p < 2; p++)
            #pragma unroll
            for (int j = 0; j < 8; j++)
                ffma2(acc[p][j], av[p], wd[j]);
    }

    float4 bb0 = *(const float4*)(bias + c0);
    float4 bb1 = *(const float4*)(bias + c0 + 4);
    float ssum[8], ssq[8];
    #pragma unroll
    for (int j = 0; j < 8; j++) { ssum[j] = 0.f; ssq[j] = 0.f; }

    int rbase = r0 + rt*4;
    int4 nv0 = *(const int4*)(nidx + rbase);
    int jns[4] = {nv0.x, nv0.y, nv0.z, nv0.w};

    #pragma unroll
    for (int i = 0; i < 4; i++) {
        int r = rbase + i;
        int n = r / MN;
        int jn = jns[i];
        const float4 p0 = *(const float4*)(g_Pself + n*C2 + c0);
        const float4 p1 = *(const float4*)(g_Pself + n*C2 + c0 + 4);
        const float4 q0 = *(const float4*)(g_Pnbr + jn*C2 + c0);
        const float4 q1 = *(const float4*)(g_Pnbr + jn*C2 + c0 + 4);
        int p = i >> 1, h = i & 1;
        float av[8];
        #pragma unroll
        for (int j = 0; j < 8; j++) {
            float2 f = lo2(acc[p][j]);
            av[j] = h ? f.y : f.x;
        }
        float gv[8];
        gv[0] = av[0] + p0.x + q0.x + bb0.x;
        gv[1] = av[1] + p0.y + q0.y + bb0.y;
        gv[2] = av[2] + p0.z + q0.z + bb0.z;
        gv[3] = av[3] + p0.w + q0.w + bb0.w;
        gv[4] = av[4] + p1.x + q1.x + bb1.x;
        gv[5] = av[5] + p1.y + q1.y + bb1.y;
        gv[6] = av[6] + p1.z + q1.z + bb1.z;
        gv[7] = av[7] + p1.w + q1.w + bb1.w;
        __half2 h0 = __floats2half2_rn(gv[0], gv[1]);
        __half2 h1 = __floats2half2_rn(gv[2], gv[3]);
        __half2 h2 = __floats2half2_rn(gv[4], gv[5]);
        __half2 h3 = __floats2half2_rn(gv[6], gv[7]);
        uint4 pk;
        pk.x = *(unsigned int*)&h0;
        pk.y = *(unsigned int*)&h1;
        pk.z = *(unsigned int*)&h2;
        pk.w = *(unsigned int*)&h3;
        *(uint4*)(g_gatedh + (size_t)r * C2 + c0) = pk;
        #pragma unroll
        for (int j = 0; j < 8; j++) { ssum[j] += gv[j]; ssq[j] += gv[j]*gv[j]; }
    }

    // deterministic block reduction: 32 rowtiles -> 1, fixed order
    #pragma unroll
    for (int j = 0; j < 8; j++) sbuf[rt*128 + c0 + j] = ssum[j];
    __syncthreads();
    if (tid < 128) {
        float t = 0.f;
        #pragma unroll
        for (int q = 0; q < 32; q++) t += sbuf[q*128 + tid];
        g_part1[tid*NB_B2 + blockIdx.x] = t;
    }
    __syncthreads();
    #pragma unroll
    for (int j = 0; j < 8; j++) sbuf[rt*128 + c0 + j] = ssq[j];
    __syncthreads();
    if (tid < 128) {
        float t = 0.f;
        #pragma unroll
        for (int q = 0; q < 32; q++) t += sbuf[q*128 + tid];
        g_part1[(128 + tid)*NB_B2 + blockIdx.x] = t;
    }
}

// ---------------- k_redcol: deterministic per-column cross-block reduce ----------------
__global__ __launch_bounds__(256) void k_redcol(int which) {
    const float* part = which ? g_part2 : g_part1;
    float* out = which ? g_red2 : g_red1;
    int nb = which ? NB_C : NB_B2;
    int c = blockIdx.x;
    const float* p = part + (size_t)c * nb;
    float a = 0.f;
    for (int i = threadIdx.x; i < nb; i += 256) a += p[i];
    __shared__ float sh[256];
    sh[threadIdx.x] = a;
    __syncthreads();
    for (int s = 128; s > 0; s >>= 1) {
        if (threadIdx.x < s) sh[threadIdx.x] += sh[threadIdx.x + s];
        __syncthreads();
    }
    if (threadIdx.x == 0) out[c] = sh[0];
}

// ---------------- bn finalize ----------------
__global__ void k_fin1(const float* __restrict__ g1, const float* __restrict__ b1) {
    int c = threadIdx.x;   // 128
    const float invn = 1.f / (float)NMROWS;
    float mu  = g_red1[c] * invn;
    float var = g_red1[128 + c] * invn - mu*mu;
    float is  = rsqrtf(var + EPSV);
    float sc  = g1[c] * is;
    g_sc1[c] = sc;
    g_sh1[c] = b1[c] - mu * sc;
}
__global__ void k_fin2(const float* __restrict__ g2, const float* __restrict__ b2) {
    int c = threadIdx.x;   // 64
    const float invn = 1.f / (float)NA;
    float mu  = g_red2[c] * invn;
    float var = g_red2[64 + c] * invn - mu*mu;
    float is  = rsqrtf(var + EPSV);
    float sc  = g2[c] * is;
    g_sc2[c] = sc;
    g_sh2[c] = b2[c] - mu * sc;
}

// ---------------- k_C: BN1 + sigmoid*softplus + sum over m + bn2 partials ----------------
// block: 16 atoms, 256 threads = 8 atom-groups (2 atoms each) x 32 f-pairs.
__global__ __launch_bounds__(256) void k_C() {
    int tid = threadIdx.x;
    int fp = tid & 31;          // f-pair index: covers f = 2fp, 2fp+1
    int ag = tid >> 5;          // 0..7
    int n0 = blockIdx.x * 16;
    int f0 = fp * 2;
    float sc0a = g_sc1[f0],     sc0b = g_sc1[f0+1];
    float sh0a = g_sh1[f0],     sh0b = g_sh1[f0+1];
    float sc1a = g_sc1[64+f0],  sc1b = g_sc1[64+f0+1];
    float sh1a = g_sh1[64+f0],  sh1b = g_sh1[64+f0+1];
    float ps0 = 0.f, ps1 = 0.f, pq0 = 0.f, pq1 = 0.f;
    __shared__ float st[1024];
    #pragma unroll
    for (int aa = 0; aa < 2; aa++) {
        int n = n0 + ag*2 + aa;
        const __half* gp = g_gatedh + (size_t)n * MN * C2;
        float s0 = 0.f, s1 = 0.f;
        #pragma unroll
        for (int m = 0; m < MN; m++) {
            __half2 u0 = *(const __half2*)(gp + m*C2 + f0);
            __half2 u1 = *(const __half2*)(gp + m*C2 + 64 + f0);
            float2 x0 = __half22float2(u0);
            float2 x1 = __half22float2(u1);
            float ya = x0.x*sc0a + sh0a, yb = x0.y*sc0b + sh0b;
            float za = x1.x*sc1a + sh1a, zb = x1.y*sc1b + sh1b;
            s0 += fsig(ya) * fsp(za);
            s1 += fsig(yb) * fsp(zb);
        }
        *(float2*)(g_summed + n*AF + f0) = make_float2(s0, s1);
        ps0 += s0; pq0 += s0*s0;
        ps1 += s1; pq1 += s1*s1;
    }
    st[ag*64 + f0]       = ps0;
    st[ag*64 + f0 + 1]   = ps1;
    st[512 + ag*64 + f0]     = pq0;
    st[512 + ag*64 + f0 + 1] = pq1;
    __syncthreads();
    if (tid < 128) {
        int w = tid >> 6, f2 = tid & 63;
        float t = 0.f;
        #pragma unroll
        for (int q = 0; q < 8; q++) t += st[w*512 + q*64 + f2];
        g_part2[(w*64 + f2)*NB_C + blockIdx.x] = t;
    }
}

// ---------------- k_update: atom = softplus(atom + bn2(summed)) ----------------
__global__ __launch_bounds__(256) void k_update() {
    int i = blockIdx.x * 256 + threadIdx.x;
    int base = i * 4;
    int c = base & 63;
    float4 a = *(const float4*)(g_atom + base);
    float4 s = *(const float4*)(g_summed + base);
    float4 sc = *(const float4*)(g_sc2 + c);
    float4 sh = *(const float4*)(g_sh2 + c);
    float4 o;
    o.x = softplusf(a.x + s.x*sc.x + sh.x);
    o.y = softplusf(a.y + s.y*sc.y + sh.y);
    o.z = softplusf(a.z + s.z*sc.z + sh.z);
    o.w = softplusf(a.w + s.w*sc.w + sh.w);
    *(float4*)(g_atom + base) = o;
}

// ---------------- k_head: pooling + softplus + FC + softplus + out ----------------
__global__ __launch_bounds__(128) void k_head(const int* __restrict__ cidx,
                                              const float* __restrict__ Wfc,
                                              const float* __restrict__ bfc,
                                              const float* __restrict__ Wout,
                                              const float* __restrict__ bout,
                                              float* __restrict__ out) {
    __shared__ float s_c[64];
    __shared__ float s_h[128];
    __shared__ float s_red[128];
    int b = blockIdx.x, t = threadIdx.x;
    int f = t & 63, half = t >> 6;
    const int* ci = cidx + b * APC;
    float acc = 0.f;
    for (int a = half*500; a < half*500 + 500; a++)
        acc += g_atom[ci[a]*AF + f];
    s_red[t] = acc;
    __syncthreads();
    if (t < 64) {
        float m = (s_red[t] + s_red[t + 64]) * (1.f / (float)APC);
        s_c[t] = softplusf(m);
    }
    __syncthreads();
    {
        float a2 = bfc[t];
        #pragma unroll 8
        for (int f2 = 0; f2 < 64; f2++) a2 += s_c[f2] * Wfc[f2*HFD + t];
        s_h[t] = softplusf(a2);
    }
    __syncthreads();
    if (t < 64) {
        float a3 = bout[t];
        #pragma unroll 8
        for (int h = 0; h < 128; h++) a3 += s_h[h] * Wout[h*HIDD + t];
        out[b*HIDD + t] = a3;
    }
}

// ---------------- launch ----------------
extern "C" void kernel_launch(void* const* d_in, const int* in_sizes, int n_in,
                              void* d_out, int out_size) {
    const int*   atom_num = (const int*)  d_in[0];
    const float* nbr_fea  = (const float*)d_in[1];
    const int*   nbr_idx  = (const int*)  d_in[2];
    const int*   cidx     = (const int*)  d_in[3];
    const float* emb      = (const float*)d_in[4];
    const float* W_full   = (const float*)d_in[5];
    const float* b_full   = (const float*)d_in[6];
    const float* bn1g     = (const float*)d_in[7];
    const float* bn1b     = (const float*)d_in[8];
    const float* bn2g     = (const float*)d_in[9];
    const float* bn2b     = (const float*)d_in[10];
    const float* W_fc     = (const float*)d_in[11];
    const float* b_fc     = (const float*)d_in[12];
    const float* W_out    = (const float*)d_in[13];
    const float* b_out    = (const float*)d_in[14];
    float* out = (float*)d_out;

    cudaFuncSetAttribute(k_A2, cudaFuncAttributeMaxDynamicSharedMemorySize, A2_SMEM_BYTES);
    cudaFuncSetAttribute(k_B,  cudaFuncAttributeMaxDynamicSharedMemorySize, B_SMEM_BYTES);

    k_embed<<<NA*AF/1024, 256>>>(atom_num, emb);
    k_prep<<<(NBR_ELEMS/4 + 255)/256, 256>>>(nbr_fea);

    for (int l = 0; l < 3; l++) {
        const float* W = W_full + l * 169 * 128;
        k_A2<<<dim3((NA + 127)/128, 2), 512, A2_SMEM_BYTES>>>(W);
        k_B<<<NB_B2, 512, B_SMEM_BYTES>>>(nbr_idx, W + 128*128, b_full + l*128);
        k_redcol<<<256, 256>>>(0);
        k_fin1<<<1, 128>>>(bn1g + l*128, bn1b + l*128);
        k_C<<<NB_C, 256>>>();
        k_redcol<<<128, 256>>>(1);
        k_fin2<<<1, 64>>>(bn2g + l*64, bn2b + l*64);
        k_update<<<NA*AF/1024, 256>>>();
    }
    k_head<<<N0C, 128>>>(cidx, W_fc, b_fc, W_out, b_out, out);
}

// round 15
// speedup vs baseline: 1.2072x; 1.2072x over previous
#include <cuda_runtime.h>
#include <cuda_fp16.h>
#include <cuda_bf16.h>
#include <cstdint>
#include <cstddef>

// ---------------- problem constants ----------------
#define NA      100000          // atoms
#define MN      12              // neighbors
#define AF      64              // atom feature len
#define NFE     41              // nbr feature len
#define C2      128             // 2*AF
#define NMROWS  (NA*MN)         // 1,200,000 edge rows
#define NB_B2   (NMROWS/128)    // 9375 blocks in gemm pass (128 rows/block)
#define NB_C2   (NA/32)         // 3125 blocks in apply pass
#define N0C     100             // crystals
#define APC     1000            // atoms per crystal
#define HFD     128
#define HIDD    64
#define EPSV    1e-5f
#define NBR_ELEMS (NMROWS*NFE)  // 49,200,000

typedef unsigned long long ull;

// ---------------- device scratch (no allocations allowed) ----------------
__device__ float  g_atom  [NA*AF];
__device__ float  g_Pself [NA*C2];
__device__ float  g_Pnbr  [NA*C2];
__device__ __half g_gatedh[(size_t)NMROWS*C2];   // 307 MB
__device__ __half g_nbrh  [NBR_ELEMS];           // 98 MB fp16 copy of nbr_fea
__device__ float  g_summed[NA*AF];
__device__ float  g_part1 [256*NB_B2];
__device__ float  g_part2 [128*NB_C2];
__device__ float  g_sc1[128], g_sh1[128];
__device__ float  g_sc2[64],  g_sh2[64];

// ---------------- helpers ----------------
__device__ __forceinline__ float softplusf(float x) {
    return fmaxf(x, 0.f) + log1pf(__expf(-fabsf(x)));
}
// fast variants for the bulk k_C pass (error ~1e-6 rel, budget 1e-3)
__device__ __forceinline__ float fsig(float x) {
    return __fdividef(1.f, 1.f + __expf(-x));
}
__device__ __forceinline__ float fsp(float x) {
    return fmaxf(x, 0.f) + __logf(1.f + __expf(-fabsf(x)));
}
// packed f32x2 FMA: d = a*b + d  (two fp32 lanes per issue slot)
__device__ __forceinline__ void ffma2(ull& d, ull a, ull b) {
    asm("fma.rn.f32x2 %0, %1, %2, %0;" : "+l"(d) : "l"(a), "l"(b));
}
__device__ __forceinline__ ull dup2(float v) {
    unsigned int u = __float_as_uint(v);
    ull r;
    asm("mov.b64 %0, {%1, %1};" : "=l"(r) : "r"(u));
    return r;
}
__device__ __forceinline__ float2 lo2(const ull& v) {
    return *reinterpret_cast<const float2*>(&v);
}

// ---------------- k_embed ----------------
__global__ __launch_bounds__(256) void k_embed(const int* __restrict__ atom_num,
                                               const float* __restrict__ emb) {
    int i = blockIdx.x * 256 + threadIdx.x;
    int base = i * 4;
    int n = base >> 6;
    int c = base & 63;
    int a = atom_num[n];
    float4 v = *(const float4*)(emb + a * AF + c);
    *(float4*)(g_atom + base) = v;
}

// ---------------- k_prep: nbr_fea fp32 -> fp16 (once) ----------------
__global__ __launch_bounds__(256) void k_prep(const float* __restrict__ nbrF) {
    int i = blockIdx.x * 256 + threadIdx.x;
    int base = i * 4;
    if (base >= NBR_ELEMS) return;
    float4 v = *(const float4*)(nbrF + base);
    __half2 h0 = __floats2half2_rn(v.x, v.y);
    __half2 h1 = __floats2half2_rn(v.z, v.w);
    uint2 o;
    o.x = *(unsigned int*)&h0;
    o.y = *(unsigned int*)&h1;
    *(uint2*)(g_nbrh + base) = o;
}

// ---------------- k_A2: Pself/Pnbr = atom_fea @ Wslab ----------------
// R13-winner config: 128x128 block, 256 threads (16x16), thread 8x8.
// Column-paired accumulators; W natural conflict-free 12-float-stride chunks;
// A natural (broadcast) + register dup.
#define A2_SMEM_A  (64*132*4)              // 33792
#define A2_SMEM_W  (64*192*4)              // 49152
#define A2_SMEM_BYTES (A2_SMEM_A + A2_SMEM_W)   // 82944
__global__ __launch_bounds__(256, 2) void k_A2(const float* __restrict__ W) {
    extern __shared__ unsigned char smraw[];
    float* sA = (float*)smraw;                  // [64 k][132 rows]
    float* sW = (float*)(smraw + A2_SMEM_A);    // [64 k][16 chunks * 12 floats]
    int tid = threadIdx.x;
    int r0 = blockIdx.x * 128;
    int half = blockIdx.y;
    const float* Wslab = W + half * 64 * 128;

    for (int idx = tid; idx < 128*64; idx += 256) {
        int row = idx >> 6, k = idx & 63;
        int r = r0 + row;
        sA[k*132 + row] = (r < NA) ? g_atom[r*AF + k] : 0.f;
    }
    for (int idx = tid; idx < 64*128; idx += 256) {
        int k = idx >> 7, cc = idx & 127;
        int c = cc >> 3, j = cc & 7;
        sW[k*192 + c*12 + j] = Wslab[k*128 + cc];
    }
    __syncthreads();

    int ct = tid & 15, rt = tid >> 4;
    int c0 = ct * 8;
    ull acc[8][4];   // [row][colpair]: lanes = cols c0+2j, c0+2j+1
    #pragma unroll
    for (int i = 0; i < 8; i++)
        #pragma unroll
        for (int j = 0; j < 4; j++) acc[i][j] = 0ULL;

    #pragma unroll 1
    for (int k = 0; k < 64; k++) {
        const float4* ap = (const float4*)(sA + k*132 + rt*8);
        float4 a03 = ap[0], a47 = ap[1];
        ull ad[8] = {dup2(a03.x), dup2(a03.y), dup2(a03.z), dup2(a03.w),
                     dup2(a47.x), dup2(a47.y), dup2(a47.z), dup2(a47.w)};
        const ulonglong2* wp = (const ulonglong2*)(sW + k*192 + ct*12);
        ulonglong2 wA = wp[0], wB = wp[1];
        ull wv[4] = {wA.x, wA.y, wB.x, wB.y};
        #pragma unroll
        for (int i = 0; i < 8; i++)
            #pragma unroll
            for (int j = 0; j < 4; j++)
                ffma2(acc[i][j], ad[i], wv[j]);
    }

    float* dst = half ? g_Pnbr : g_Pself;
    #pragma unroll
    for (int i = 0; i < 8; i++) {
        int r = r0 + rt*8 + i;
        if (r < NA) {
            float2 f0 = lo2(acc[i][0]), f1 = lo2(acc[i][1]);
            float2 f2 = lo2(acc[i][2]), f3 = lo2(acc[i][3]);
            float* p = dst + r*C2 + c0;
            *(float4*)(p)     = make_float4(f0.x, f0.y, f1.x, f1.y);
            *(float4*)(p + 4) = make_float4(f2.x, f2.y, f3.x, f3.y);
        }
    }
}

// ---------------- k_B: edge GEMM + assemble gated(fp16) + bn1 partial stats ----------------
// block: 128 edge-rows x 128 cols, 256 threads (16x16), thread 8x8.
// Column-paired accumulators; A DUPLICATED in smem ({v,v} pairs, broadcast reads,
// zero MOVs in mainloop); W natural conflict-free 12-float-stride chunks.
#define B_SMEM_A   (41*132*8)              // 43296 (dup pairs, stride 132 ull)
#define B_SMEM_W   (41*192*4)              // 31488
#define B_SMEM_BYTES (B_SMEM_A + B_SMEM_W + 16*128*4)   // + sbuf 8192 = 82976
__global__ __launch_bounds__(256, 2) void k_B(const int*   __restrict__ nidx,
                                              const float* __restrict__ Wnf,
                                              const float* __restrict__ bias) {
    extern __shared__ unsigned char smraw[];
    ull*   sA2  = (ull*)smraw;                            // [41 k][132 rows] dup pairs
    float* sW   = (float*)(smraw + B_SMEM_A);             // [41 k][16 chunks * 12]
    float* sbuf = (float*)(smraw + B_SMEM_A + B_SMEM_W);  // [16][128]
    int tid = threadIdx.x;
    int r0 = blockIdx.x * 128;

    const __half* src = g_nbrh + (size_t)r0 * NFE;   // 128 contiguous rows
    for (int idx = tid; idx < 128*41; idx += 256) {
        int row = idx / 41, k = idx - row*41;
        sA2[k*132 + row] = dup2(__half2float(src[idx]));
    }
    for (int idx = tid; idx < 41*128; idx += 256) {
        int k = idx >> 7, cc = idx & 127;
        int c = cc >> 3, j = cc & 7;
        sW[k*192 + c*12 + j] = Wnf[k*128 + cc];
    }
    __syncthreads();

    int ct = tid & 15, rt = tid >> 4;
    int c0 = ct * 8;
    ull acc[8][4];   // [row][colpair]
    #pragma unroll
    for (int i = 0; i < 8; i++)
        #pragma unroll
        for (int j = 0; j < 4; j++) acc[i][j] = 0ULL;

    #pragma unroll 2
    for (int k = 0; k < 41; k++) {
        const ulonglong2* ap = (const ulonglong2*)(sA2 + k*132 + rt*8);
        ulonglong2 aA = ap[0], aB = ap[1], aC = ap[2], aD = ap[3];
        ull ad[8] = {aA.x, aA.y, aB.x, aB.y, aC.x, aC.y, aD.x, aD.y};
        const ulonglong2* wp = (const ulonglong2*)(sW + k*192 + ct*12);
        ulonglong2 wA = wp[0], wB = wp[1];
        ull wv[4] = {wA.x, wA.y, wB.x, wB.y};
        #pragma unroll
        for (int i = 0; i < 8; i++)
            #pragma unroll
            for (int j = 0; j < 4; j++)
                ffma2(acc[i][j], ad[i], wv[j]);
    }

    float4 bb0 = *(const float4*)(bias + c0);
    float4 bb1 = *(const float4*)(bias + c0 + 4);
    float ssum[8], ssq[8];
    #pragma unroll
    for (int j = 0; j < 8; j++) { ssum[j] = 0.f; ssq[j] = 0.f; }

    int rbase = r0 + rt*8;
    int4 nv0 = *(const int4*)(nidx + rbase);
    int4 nv1 = *(const int4*)(nidx + rbase + 4);
    int jns[8] = {nv0.x, nv0.y, nv0.z, nv0.w, nv1.x, nv1.y, nv1.z, nv1.w};

    #pragma unroll
    for (int i = 0; i < 8; i++) {
        int r = rbase + i;
        int n = r / MN;
        int jn = jns[i];
        const float4 p0 = *(const float4*)(g_Pself + n*C2 + c0);
        const float4 p1 = *(const float4*)(g_Pself + n*C2 + c0 + 4);
        const float4 q0 = *(const float4*)(g_Pnbr + jn*C2 + c0);
        const float4 q1 = *(const float4*)(g_Pnbr + jn*C2 + c0 + 4);
        float2 f0 = lo2(acc[i][0]), f1 = lo2(acc[i][1]);
        float2 f2 = lo2(acc[i][2]), f3 = lo2(acc[i][3]);
        float gv[8];
        gv[0] = f0.x + p0.x + q0.x + bb0.x;
        gv[1] = f0.y + p0.y + q0.y + bb0.y;
        gv[2] = f1.x + p0.z + q0.z + bb0.z;
        gv[3] = f1.y + p0.w + q0.w + bb0.w;
        gv[4] = f2.x + p1.x + q1.x + bb1.x;
        gv[5] = f2.y + p1.y + q1.y + bb1.y;
        gv[6] = f3.x + p1.z + q1.z + bb1.z;
        gv[7] = f3.y + p1.w + q1.w + bb1.w;
        __half2 h0 = __floats2half2_rn(gv[0], gv[1]);
        __half2 h1 = __floats2half2_rn(gv[2], gv[3]);
        __half2 h2 = __floats2half2_rn(gv[4], gv[5]);
        __half2 h3 = __floats2half2_rn(gv[6], gv[7]);
        uint4 pk;
        pk.x = *(unsigned int*)&h0;
        pk.y = *(unsigned int*)&h1;
        pk.z = *(unsigned int*)&h2;
        pk.w = *(unsigned int*)&h3;
        *(uint4*)(g_gatedh + (size_t)r * C2 + c0) = pk;
        #pragma unroll
        for (int j = 0; j < 8; j++) { ssum[j] += gv[j]; ssq[j] += gv[j]*gv[j]; }
    }

    // deterministic block reduction: 16 rowtiles -> 1, fixed order
    #pragma unroll
    for (int j = 0; j < 8; j++) sbuf[rt*128 + c0 + j] = ssum[j];
    __syncthreads();
    if (tid < 128) {
        float t = 0.f;
        #pragma unroll
        for (int q = 0; q < 16; q++) t += sbuf[q*128 + tid];
        g_part1[tid*NB_B2 + blockIdx.x] = t;
    }
    __syncthreads();
    #pragma unroll
    for (int j = 0; j < 8; j++) sbuf[rt*128 + c0 + j] = ssq[j];
    __syncthreads();
    if (tid < 128) {
        float t = 0.f;
        #pragma unroll
        for (int q = 0; q < 16; q++) t += sbuf[q*128 + tid];
        g_part1[(128 + tid)*NB_B2 + blockIdx.x] = t;
    }
}

// ---------------- k_stats1: fused per-column reduce + bn1 finalize ----------------
// 128 blocks; block c reduces sum (row c) and sumsq (row 128+c) of g_part1,
// then writes g_sc1[c], g_sh1[c]. Deterministic: strided + fixed tree.
__global__ __launch_bounds__(256) void k_stats1(const float* __restrict__ g1,
                                                const float* __restrict__ b1) {
    int c = blockIdx.x;
    int tid = threadIdx.x;
    const float* ps = g_part1 + (size_t)c * NB_B2;
    const float* pq = g_part1 + (size_t)(128 + c) * NB_B2;
    float a = 0.f, b = 0.f;
    for (int i = tid; i < NB_B2; i += 256) { a += ps[i]; b += pq[i]; }
    __shared__ float sa[256], sb[256];
    sa[tid] = a; sb[tid] = b;
    __syncthreads();
    for (int s = 128; s > 0; s >>= 1) {
        if (tid < s) { sa[tid] += sa[tid + s]; sb[tid] += sb[tid + s]; }
        __syncthreads();
    }
    if (tid == 0) {
        const float invn = 1.f / (float)NMROWS;
        float mu  = sa[0] * invn;
        float var = sb[0] * invn - mu*mu;
        float is  = rsqrtf(var + EPSV);
        float sc  = g1[c] * is;
        g_sc1[c] = sc;
        g_sh1[c] = b1[c] - mu * sc;
    }
}

// ---------------- k_stats2: fused per-column reduce + bn2 finalize ----------------
__global__ __launch_bounds__(256) void k_stats2(const float* __restrict__ g2,
                                                const float* __restrict__ b2) {
    int c = blockIdx.x;   // 0..63
    int tid = threadIdx.x;
    const float* ps = g_part2 + (size_t)c * NB_C2;
    const float* pq = g_part2 + (size_t)(64 + c) * NB_C2;
    float a = 0.f, b = 0.f;
    for (int i = tid; i < NB_C2; i += 256) { a += ps[i]; b += pq[i]; }
    __shared__ float sa[256], sb[256];
    sa[tid] = a; sb[tid] = b;
    __syncthreads();
    for (int s = 128; s > 0; s >>= 1) {
        if (tid < s) { sa[tid] += sa[tid + s]; sb[tid] += sb[tid + s]; }
        __syncthreads();
    }
    if (tid == 0) {
        const float invn = 1.f / (float)NA;
        float mu  = sa[0] * invn;
        float var = sb[0] * invn - mu*mu;
        float is  = rsqrtf(var + EPSV);
        float sc  = g2[c] * is;
        g_sc2[c] = sc;
        g_sh2[c] = b2[c] - mu * sc;
    }
}

// ---------------- k_C: BN1 + sigmoid*softplus + sum over m + bn2 partials ----------------
// block: 32 atoms, 256 threads = 8 f-chunks x 32 atoms; uint4 (8-half) loads.
__global__ __launch_bounds__(256) void k_C() {
    int tid = threadIdx.x;
    int c  = tid & 7;           // f-chunk: f = c*8 .. c*8+7
    int ag = tid >> 3;          // atom in block 0..31
    int n  = blockIdx.x * 32 + ag;
    int f0 = c * 8;
    float4 scf0 = *(const float4*)(g_sc1 + f0);
    float4 scf1 = *(const float4*)(g_sc1 + f0 + 4);
    float4 shf0 = *(const float4*)(g_sh1 + f0);
    float4 shf1 = *(const float4*)(g_sh1 + f0 + 4);
    float4 scc0 = *(const float4*)(g_sc1 + 64 + f0);
    float4 scc1 = *(const float4*)(g_sc1 + 64 + f0 + 4);
    float4 shc0 = *(const float4*)(g_sh1 + 64 + f0);
    float4 shc1 = *(const float4*)(g_sh1 + 64 + f0 + 4);

    const __half* gp = g_gatedh + (size_t)n * MN * C2;
    float s[8];
    #pragma unroll
    for (int j = 0; j < 8; j++) s[j] = 0.f;

    #pragma unroll
    for (int m = 0; m < MN; m++) {
        uint4 uf = *(const uint4*)(gp + m*C2 + f0);
        uint4 uc = *(const uint4*)(gp + m*C2 + 64 + f0);
        float2 xf0 = __half22float2(*(const __half2*)&uf.x);
        float2 xf1 = __half22float2(*(const __half2*)&uf.y);
        float2 xf2 = __half22float2(*(const __half2*)&uf.z);
        float2 xf3 = __half22float2(*(const __half2*)&uf.w);
        float2 xc0 = __half22float2(*(const __half2*)&uc.x);
        float2 xc1 = __half22float2(*(const __half2*)&uc.y);
        float2 xc2 = __half22float2(*(const __half2*)&uc.z);
        float2 xc3 = __half22float2(*(const __half2*)&uc.w);
        s[0] += fsig(xf0.x*scf0.x + shf0.x) * fsp(xc0.x*scc0.x + shc0.x);
        s[1] += fsig(xf0.y*scf0.y + shf0.y) * fsp(xc0.y*scc0.y + shc0.y);
        s[2] += fsig(xf1.x*scf0.z + shf0.z) * fsp(xc1.x*scc0.z + shc0.z);
        s[3] += fsig(xf1.y*scf0.w + shf0.w) * fsp(xc1.y*scc0.w + shc0.w);
        s[4] += fsig(xf2.x*scf1.x + shf1.x) * fsp(xc2.x*scc1.x + shc1.x);
        s[5] += fsig(xf2.y*scf1.y + shf1.y) * fsp(xc2.y*scc1.y + shc1.y);
        s[6] += fsig(xf3.x*scf1.z + shf1.z) * fsp(xc3.x*scc1.z + shc1.z);
        s[7] += fsig(xf3.y*scf1.w + shf1.w) * fsp(xc3.y*scc1.w + shc1.w);
    }

    float* sp_ = g_summed + n*AF + f0;
    *(float4*)(sp_)     = make_float4(s[0], s[1], s[2], s[3]);
    *(float4*)(sp_ + 4) = make_float4(s[4], s[5], s[6], s[7]);

    // bn2 partial stats: per (atom, f) value -> column sums over 32 atoms
    __shared__ float st[2*32*64];   // 16 KB: [sum|sq][ag][f]
    #pragma unroll
    for (int j = 0; j < 8; j++) {
        st[ag*64 + f0 + j]        = s[j];
        st[2048 + ag*64 + f0 + j] = s[j]*s[j];
    }
    __syncthreads();
    if (tid < 128) {
        int w = tid >> 6, f = tid & 63;
        float t = 0.f;
        #pragma unroll
        for (int q = 0; q < 32; q++) t += st[w*2048 + q*64 + f];
        g_part2[(w*64 + f)*NB_C2 + blockIdx.x] = t;
    }
}

// ---------------- k_update: atom = softplus(atom + bn2(summed)) ----------------
__global__ __launch_bounds__(256) void k_update() {
    int i = blockIdx.x * 256 + threadIdx.x;
    int base = i * 4;
    int c = base & 63;
    float4 a = *(const float4*)(g_atom + base);
    float4 s = *(const float4*)(g_summed + base);
    float4 sc = *(const float4*)(g_sc2 + c);
    float4 sh = *(const float4*)(g_sh2 + c);
    float4 o;
    o.x = softplusf(a.x + s.x*sc.x + sh.x);
    o.y = softplusf(a.y + s.y*sc.y + sh.y);
    o.z = softplusf(a.z + s.z*sc.z + sh.z);
    o.w = softplusf(a.w + s.w*sc.w + sh.w);
    *(float4*)(g_atom + base) = o;
}

// ---------------- k_head: pooling + softplus + FC + softplus + out ----------------
__global__ __launch_bounds__(128) void k_head(const int* __restrict__ cidx,
                                              const float* __restrict__ Wfc,
                                              const float* __restrict__ bfc,
                                              const float* __restrict__ Wout,
                                              const float* __restrict__ bout,
                                              float* __restrict__ out) {
    __shared__ float s_c[64];
    __shared__ float s_h[128];
    __shared__ float s_red[128];
    int b = blockIdx.x, t = threadIdx.x;
    int f = t & 63, half = t >> 6;
    const int* ci = cidx + b * APC;
    float acc = 0.f;
    for (int a = half*500; a < half*500 + 500; a++)
        acc += g_atom[ci[a]*AF + f];
    s_red[t] = acc;
    __syncthreads();
    if (t < 64) {
        float m = (s_red[t] + s_red[t + 64]) * (1.f / (float)APC);
        s_c[t] = softplusf(m);
    }
    __syncthreads();
    {
        float a2 = bfc[t];
        #pragma unroll 8
        for (int f2 = 0; f2 < 64; f2++) a2 += s_c[f2] * Wfc[f2*HFD + t];
        s_h[t] = softplusf(a2);
    }
    __syncthreads();
    if (t < 64) {
        float a3 = bout[t];
        #pragma unroll 8
        for (int h = 0; h < 128; h++) a3 += s_h[h] * Wout[h*HIDD + t];
        out[b*HIDD + t] = a3;
    }
}

// ---------------- launch ----------------
extern "C" void kernel_launch(void* const* d_in, const int* in_sizes, int n_in,
                              void* d_out, int out_size) {
    const int*   atom_num = (const int*)  d_in[0];
    const float* nbr_fea  = (const float*)d_in[1];
    const int*   nbr_idx  = (const int*)  d_in[2];
    const int*   cidx     = (const int*)  d_in[3];
    const float* emb      = (const float*)d_in[4];
    const float* W_full   = (const float*)d_in[5];
    const float* b_full   = (const float*)d_in[6];
    const float* bn1g     = (const float*)d_in[7];
    const float* bn1b     = (const float*)d_in[8];
    const float* bn2g     = (const float*)d_in[9];
    const float* bn2b     = (const float*)d_in[10];
    const float* W_fc     = (const float*)d_in[11];
    const float* b_fc     = (const float*)d_in[12];
    const float* W_out    = (const float*)d_in[13];
    const float* b_out    = (const float*)d_in[14];
    float* out = (float*)d_out;

    cudaFuncSetAttribute(k_A2, cudaFuncAttributeMaxDynamicSharedMemorySize, A2_SMEM_BYTES);
    cudaFuncSetAttribute(k_B,  cudaFuncAttributeMaxDynamicSharedMemorySize, B_SMEM_BYTES);

    k_embed<<<NA*AF/1024, 256>>>(atom_num, emb);
    k_prep<<<(NBR_ELEMS/4 + 255)/256, 256>>>(nbr_fea);

    for (int l = 0; l < 3; l++) {
        const float* W = W_full + l * 169 * 128;
        k_A2<<<dim3((NA + 127)/128, 2), 256, A2_SMEM_BYTES>>>(W);
        k_B<<<NB_B2, 256, B_SMEM_BYTES>>>(nbr_idx, W + 128*128, b_full + l*128);
        k_stats1<<<128, 256>>>(bn1g + l*128, bn1b + l*128);
        k_C<<<NB_C2, 256>>>();
        k_stats2<<<64, 256>>>(bn2g + l*64, bn2b + l*64);
        k_update<<<NA*AF/1024, 256>>>();
    }
    k_head<<<N0C, 128>>>(cidx, W_fc, b_fc, W_out, b_out, out);
}